// round 14
// baseline (speedup 1.0000x reference)
#include <cuda_runtime.h>

// Problem constants
#define BATCH  2
#define SEQ    2048
#define DMODEL 1024
#define NHEAD  16
#define HSIZE  64
#define MTOT   (BATCH*SEQ)   // 4096

// Scratch (device globals: allocation-free per harness rules)
__device__ float g_Q[BATCH*NHEAD*SEQ*HSIZE];  // [B,H,S,HS]
__device__ float g_K[BATCH*NHEAD*SEQ*HSIZE];
__device__ float g_V[BATCH*NHEAD*SEQ*HSIZE];
__device__ float g_O[(size_t)MTOT*DMODEL];    // [B*S, D]

struct QKVArgs {
    const float* W[3];
    const float* bias[3];
    float*       C[3];
};

// ---------------------------------------------------------------------------
// TF32 / math helpers
// ---------------------------------------------------------------------------
__device__ __forceinline__ float tf32r(float x) {  // round to tf32, keep float bits
    unsigned u;
    asm("cvt.rna.tf32.f32 %0, %1;" : "=r"(u) : "f"(x));
    return __uint_as_float(u);
}

__device__ __forceinline__ float fexp2(float x) {  // raw MUFU ex2
    float y;
    asm("ex2.approx.ftz.f32 %0, %1;" : "=f"(y) : "f"(x));
    return y;
}

__device__ __forceinline__ void mma_tf32_16x8x8(
    float c[4], const unsigned a[4], const unsigned b[2])
{
    asm volatile(
        "mma.sync.aligned.m16n8k8.row.col.f32.tf32.tf32.f32 "
        "{%0,%1,%2,%3}, {%4,%5,%6,%7}, {%8,%9}, {%0,%1,%2,%3};\n"
        : "+f"(c[0]), "+f"(c[1]), "+f"(c[2]), "+f"(c[3])
        : "r"(a[0]), "r"(a[1]), "r"(a[2]), "r"(a[3]),
          "r"(b[0]), "r"(b[1]));
}

#define FAU(x) __float_as_uint(x)

// ---------------------------------------------------------------------------
// TF32 GEMM body: C[4096,1024] = A[4096,1024] @ W[1024,1024] + bias
// BM=BN=128, BK=8, 256 thr = 8 warps (4 x 2); warp tile 32x64 = 2x8 mmas.
// Double-buffered smem (tf32-preconverted), register prefetch, 1 barrier/step.
// A stride 12 (bank 12g+t: perfect permutation) and B stride 136 (bank 8t+g):
// fragment LDS conflict-free (mod-32 verified).
// PERM=true scatters output into [B,H,S,HS] layout for attention.
// ---------------------------------------------------------------------------
#define ASTRIDE 12
#define BSTRIDE 136

template<bool PERM>
__device__ __forceinline__ void tf32_gemm_body(
    const float* __restrict__ A, const float* __restrict__ Bm,
    const float* __restrict__ bias, float* __restrict__ C)
{
    __shared__ float As[2][128*ASTRIDE];   // [m][k] padded, tf32 values
    __shared__ float Bs[2][8*BSTRIDE];     // [k][n] padded, tf32 values

    const int bm   = blockIdx.y * 128;
    const int bn   = blockIdx.x * 128;
    const int tid  = threadIdx.x;
    const int lane = tid & 31;
    const int warp = tid >> 5;
    const int wm   = warp & 3;    // 0..3 -> M offset wm*32
    const int wn   = warp >> 2;   // 0..1 -> N offset wn*64

    const int g = lane >> 2;      // 0..7
    const int t = lane & 3;       // 0..3

    const int arow = tid >> 1;           // 0..127
    const int acol = (tid & 1) << 2;     // 0 or 4
    const int brow = tid >> 5;           // 0..7
    const int bcol = (tid & 31) << 2;    // 0..124

    const float* Ap = A  + (size_t)(bm + arow) * DMODEL + acol;
    const float* Bp = Bm + (size_t)brow * DMODEL + bn + bcol;

    float acc[2][8][4];
    #pragma unroll
    for (int mt = 0; mt < 2; ++mt)
        #pragma unroll
        for (int nt = 0; nt < 8; ++nt)
            #pragma unroll
            for (int r = 0; r < 4; ++r) acc[mt][nt][r] = 0.f;

    // Prologue: fill buffer 0 (converted)
    {
        float4 av = *(const float4*)(Ap);
        float4 bv = *(const float4*)(Bp);
        float4 ac = make_float4(tf32r(av.x), tf32r(av.y), tf32r(av.z), tf32r(av.w));
        float4 bc = make_float4(tf32r(bv.x), tf32r(bv.y), tf32r(bv.z), tf32r(bv.w));
        *(float4*)&As[0][arow*ASTRIDE + acol] = ac;
        *(float4*)&Bs[0][brow*BSTRIDE + bcol] = bc;
    }
    __syncthreads();

    int buf = 0;
    for (int k0 = 8; ; k0 += 8) {
        const bool more = (k0 < DMODEL);
        float4 av2, bv2;
        if (more) {
            av2 = *(const float4*)(Ap + k0);
            bv2 = *(const float4*)(Bp + (size_t)k0 * DMODEL);
        }

        unsigned aF[2][4];
        #pragma unroll
        for (int mt = 0; mt < 2; ++mt) {
            const int r0 = wm*32 + mt*16 + g;
            aF[mt][0] = FAU(As[buf][(r0    )*ASTRIDE + t    ]);
            aF[mt][1] = FAU(As[buf][(r0 + 8)*ASTRIDE + t    ]);
            aF[mt][2] = FAU(As[buf][(r0    )*ASTRIDE + t + 4]);
            aF[mt][3] = FAU(As[buf][(r0 + 8)*ASTRIDE + t + 4]);
        }
        #pragma unroll
        for (int nt = 0; nt < 8; ++nt) {
            const int c0 = wn*64 + nt*8 + g;
            unsigned bF[2];
            bF[0] = FAU(Bs[buf][(t    )*BSTRIDE + c0]);
            bF[1] = FAU(Bs[buf][(t + 4)*BSTRIDE + c0]);
            mma_tf32_16x8x8(acc[0][nt], aF[0], bF);
            mma_tf32_16x8x8(acc[1][nt], aF[1], bF);
        }

        if (!more) break;

        const int nb = buf ^ 1;
        float4 ac = make_float4(tf32r(av2.x), tf32r(av2.y), tf32r(av2.z), tf32r(av2.w));
        float4 bc = make_float4(tf32r(bv2.x), tf32r(bv2.y), tf32r(bv2.z), tf32r(bv2.w));
        *(float4*)&As[nb][arow*ASTRIDE + acol] = ac;
        *(float4*)&Bs[nb][brow*BSTRIDE + bcol] = bc;
        __syncthreads();
        buf = nb;
    }

    // Epilogue: c0,c1 at (row, 2t), (row, 2t+1); c2,c3 at row+8
    #pragma unroll
    for (int mt = 0; mt < 2; ++mt) {
        #pragma unroll
        for (int nt = 0; nt < 8; ++nt) {
            const int c = bn + wn*64 + nt*8 + 2*t;
            const float bx = bias[c], by = bias[c+1];
            #pragma unroll
            for (int half = 0; half < 2; ++half) {
                const int r = bm + wm*32 + mt*16 + g + half*8;
                float2 v;
                v.x = acc[mt][nt][half*2+0] + bx;
                v.y = acc[mt][nt][half*2+1] + by;
                if (PERM) {
                    const int b  = r >> 11;       // r / SEQ
                    const int s  = r & (SEQ-1);
                    const int h  = c >> 6;        // c / HSIZE
                    const int hs = c & 63;
                    *(float2*)&C[(((size_t)(b*NHEAD + h))*SEQ + s)*HSIZE + hs] = v;
                } else {
                    *(float2*)&C[(size_t)r*DMODEL + c] = v;
                }
            }
        }
    }
}

__global__ __launch_bounds__(256, 2) void qkv_kernel(
    const float* __restrict__ A, QKVArgs args)
{
    const int z = blockIdx.z;
    tf32_gemm_body<true>(A, args.W[z], args.bias[z], args.C[z]);
}

__global__ __launch_bounds__(256, 2) void oproj_kernel(
    const float* __restrict__ A, const float* __restrict__ W,
    const float* __restrict__ bias, float* __restrict__ C)
{
    tf32_gemm_body<false>(A, W, bias, C);
}

// ---------------------------------------------------------------------------
// TF32-mma causal flash attention.
// CTA = 128 q-rows x one (b,h). 256 threads = 8 warps; warp w owns q-rows
// [w*16, w*16+16) and the full 64-key / 64-hs extent.
// Row-major smem tiles with stride 72 (72 = 8 mod 32):
//   K B-frags: bank = 8g+t  -> conflict-free
//   V B-frags: bank = 8t+g  -> conflict-free
//   Q/P A-frags: bank = 8g+t (+8ks) -> conflict-free
// Softmax in exp2 domain (log2(e)/8 folded into Q scale).
// P staged through warp-private smem rows (-> __syncwarp only).
// Fully-masked warps on trailing tiles skip compute.
// smem: (128+64+64+128) rows x 72 floats = 110592 B -> 2 CTAs/SM.
// ---------------------------------------------------------------------------
#define FSTR 72
#define FLASH_SMEM_FLOATS (384*FSTR)
#define FLASH_SMEM_BYTES  (FLASH_SMEM_FLOATS*4)   // 110592
#define QSCALE (0.125f * 1.4426950408889634f)     // 1/sqrt(64) * log2(e)

__global__ __launch_bounds__(256, 2) void flash_kernel(
    const float* __restrict__ Q, const float* __restrict__ K,
    const float* __restrict__ V, float* __restrict__ O)
{
    extern __shared__ float sm[];
    float* Qs = sm;                  // [q][d]    tf32, scaled by QSCALE
    float* Ks = sm + 128*FSTR;       // [key][d]  tf32
    float* Vs = sm + 192*FSTR;       // [key][hs] tf32
    float* Ps = sm + 256*FSTR;       // [q][key]  tf32

    const int qtile = (gridDim.x - 1) - blockIdx.x;  // heavy tiles first
    const int bh    = blockIdx.y;
    const int tid   = threadIdx.x;
    const int lane  = tid & 31;
    const int warp  = tid >> 5;      // 0..7
    const int g     = lane >> 2;     // 0..7
    const int t     = lane & 3;      // 0..3
    const int qr    = warp * 16;     // warp's local q-row base

    const size_t base = (size_t)bh * SEQ * HSIZE;
    const float* Qb = Q + base;
    const float* Kb = K + base;
    const float* Vb = V + base;
    const int q0 = qtile * 128;

    // Load Q tile [128][64], fold QSCALE, convert to tf32
    for (int idx = tid; idx < 2048; idx += 256) {
        const int r = idx >> 4;
        const int c = (idx & 15) << 2;
        float4 v = *(const float4*)(Qb + (size_t)(q0 + r)*HSIZE + c);
        float* dst = &Qs[r*FSTR + c];
        dst[0] = tf32r(v.x * QSCALE);
        dst[1] = tf32r(v.y * QSCALE);
        dst[2] = tf32r(v.z * QSCALE);
        dst[3] = tf32r(v.w * QSCALE);
    }

    float oF[8][4];
    #pragma unroll
    for (int nt = 0; nt < 8; ++nt)
        #pragma unroll
        for (int r = 0; r < 4; ++r) oF[nt][r] = 0.f;
    float m0 = -1e30f, m1 = -1e30f, l0 = 0.f, l1 = 0.f;

    const int nkt = 2*qtile + 2;     // key tiles covering [0, q0+128)
    for (int kt = 0; kt < nkt; ++kt) {
        __syncthreads();             // prior tile reads done (Qs ready 1st iter)
        const int k0 = kt * 64;

        // Load K and V tiles row-major, tf32-converted (coalesced float4)
        for (int idx = tid; idx < 1024; idx += 256) {
            const int r = idx >> 4;
            const int c = (idx & 15) << 2;
            float4 kv = *(const float4*)(Kb + (size_t)(k0 + r)*HSIZE + c);
            float* kd = &Ks[r*FSTR + c];
            kd[0] = tf32r(kv.x);
            kd[1] = tf32r(kv.y);
            kd[2] = tf32r(kv.z);
            kd[3] = tf32r(kv.w);
            float4 vv = *(const float4*)(Vb + (size_t)(k0 + r)*HSIZE + c);
            float* vd = &Vs[r*FSTR + c];
            vd[0] = tf32r(vv.x);
            vd[1] = tf32r(vv.y);
            vd[2] = tf32r(vv.z);
            vd[3] = tf32r(vv.w);
        }
        __syncthreads();

        // Warp fully below the diagonal band? Skip all compute.
        if (q0 + qr + 15 < k0) continue;

        // ---- S' = (Q*QSCALE) K^T  (log2-domain scores) ----
        float sF[8][4];
        #pragma unroll
        for (int nt = 0; nt < 8; ++nt)
            #pragma unroll
            for (int r = 0; r < 4; ++r) sF[nt][r] = 0.f;

        #pragma unroll
        for (int ks = 0; ks < 8; ++ks) {
            unsigned aF[4];
            aF[0] = FAU(Qs[(qr+g  )*FSTR + ks*8 + t    ]);
            aF[1] = FAU(Qs[(qr+g+8)*FSTR + ks*8 + t    ]);
            aF[2] = FAU(Qs[(qr+g  )*FSTR + ks*8 + t + 4]);
            aF[3] = FAU(Qs[(qr+g+8)*FSTR + ks*8 + t + 4]);
            #pragma unroll
            for (int nt = 0; nt < 8; ++nt) {
                unsigned bF[2];
                bF[0] = FAU(Ks[(nt*8 + g)*FSTR + ks*8 + t    ]);
                bF[1] = FAU(Ks[(nt*8 + g)*FSTR + ks*8 + t + 4]);
                mma_tf32_16x8x8(sF[nt], aF, bF);
            }
        }

        // ---- causal mask (only tiles straddling the diagonal) ----
        const int qg0 = q0 + qr + g;
        const int qg1 = qg0 + 8;
        if (k0 + 63 > q0 + qr) {
            #pragma unroll
            for (int nt = 0; nt < 8; ++nt) {
                const int j0 = k0 + nt*8 + 2*t;
                if (j0     > qg0) sF[nt][0] = -1e30f;
                if (j0 + 1 > qg0) sF[nt][1] = -1e30f;
                if (j0     > qg1) sF[nt][2] = -1e30f;
                if (j0 + 1 > qg1) sF[nt][3] = -1e30f;
            }
        }

        // ---- online softmax in exp2 domain (rows g and g+8) ----
        float mt0 = -1e30f, mt1 = -1e30f;
        #pragma unroll
        for (int nt = 0; nt < 8; ++nt) {
            mt0 = fmaxf(mt0, fmaxf(sF[nt][0], sF[nt][1]));
            mt1 = fmaxf(mt1, fmaxf(sF[nt][2], sF[nt][3]));
        }
        mt0 = fmaxf(mt0, __shfl_xor_sync(0xffffffffu, mt0, 1));
        mt0 = fmaxf(mt0, __shfl_xor_sync(0xffffffffu, mt0, 2));
        mt1 = fmaxf(mt1, __shfl_xor_sync(0xffffffffu, mt1, 1));
        mt1 = fmaxf(mt1, __shfl_xor_sync(0xffffffffu, mt1, 2));

        const float m0n = fmaxf(m0, mt0);
        const float m1n = fmaxf(m1, mt1);
        const float sc0 = fexp2(m0 - m0n);
        const float sc1 = fexp2(m1 - m1n);

        float rs0 = 0.f, rs1 = 0.f;
        #pragma unroll
        for (int nt = 0; nt < 8; ++nt) {
            sF[nt][0] = fexp2(sF[nt][0] - m0n); rs0 += sF[nt][0];
            sF[nt][1] = fexp2(sF[nt][1] - m0n); rs0 += sF[nt][1];
            sF[nt][2] = fexp2(sF[nt][2] - m1n); rs1 += sF[nt][2];
            sF[nt][3] = fexp2(sF[nt][3] - m1n); rs1 += sF[nt][3];
        }
        rs0 += __shfl_xor_sync(0xffffffffu, rs0, 1);
        rs0 += __shfl_xor_sync(0xffffffffu, rs0, 2);
        rs1 += __shfl_xor_sync(0xffffffffu, rs1, 1);
        rs1 += __shfl_xor_sync(0xffffffffu, rs1, 2);

        l0 = l0*sc0 + rs0;  m0 = m0n;
        l1 = l1*sc1 + rs1;  m1 = m1n;

        #pragma unroll
        for (int nt = 0; nt < 8; ++nt) {
            oF[nt][0] *= sc0; oF[nt][1] *= sc0;
            oF[nt][2] *= sc1; oF[nt][3] *= sc1;
        }

        // ---- stage P (tf32) into warp-private smem rows ----
        #pragma unroll
        for (int nt = 0; nt < 8; ++nt) {
            float2 p0; p0.x = tf32r(sF[nt][0]); p0.y = tf32r(sF[nt][1]);
            float2 p1; p1.x = tf32r(sF[nt][2]); p1.y = tf32r(sF[nt][3]);
            *(float2*)&Ps[(qr+g  )*FSTR + nt*8 + 2*t] = p0;
            *(float2*)&Ps[(qr+g+8)*FSTR + nt*8 + 2*t] = p1;
        }
        __syncwarp();

        // ---- O += P @ V ----
        #pragma unroll
        for (int ks = 0; ks < 8; ++ks) {
            unsigned aP[4];
            aP[0] = FAU(Ps[(qr+g  )*FSTR + ks*8 + t    ]);
            aP[1] = FAU(Ps[(qr+g+8)*FSTR + ks*8 + t    ]);
            aP[2] = FAU(Ps[(qr+g  )*FSTR + ks*8 + t + 4]);
            aP[3] = FAU(Ps[(qr+g+8)*FSTR + ks*8 + t + 4]);
            #pragma unroll
            for (int nt = 0; nt < 8; ++nt) {
                unsigned bV[2];
                bV[0] = FAU(Vs[(ks*8 + t    )*FSTR + nt*8 + g]);
                bV[1] = FAU(Vs[(ks*8 + t + 4)*FSTR + nt*8 + g]);
                mma_tf32_16x8x8(oF[nt], aP, bV);
            }
        }
    }

    // ---- epilogue: normalize, write [B*S, D] scratch ----
    const int bidx = bh >> 4;
    const int h    = bh & 15;
    const int qg0  = q0 + qr + g;
    const int qg1  = qg0 + 8;
    const float inv0 = 1.f / l0;
    const float inv1 = 1.f / l1;
    #pragma unroll
    for (int nt = 0; nt < 8; ++nt) {
        const int c = h*HSIZE + nt*8 + 2*t;
        float2 v0; v0.x = oF[nt][0]*inv0; v0.y = oF[nt][1]*inv0;
        float2 v1; v1.x = oF[nt][2]*inv1; v1.y = oF[nt][3]*inv1;
        *(float2*)&O[((size_t)(bidx*SEQ + qg0))*DMODEL + c] = v0;
        *(float2*)&O[((size_t)(bidx*SEQ + qg1))*DMODEL + c] = v1;
    }
}

// ---------------------------------------------------------------------------
extern "C" void kernel_launch(void* const* d_in, const int* in_sizes, int n_in,
                              void* d_out, int out_size)
{
    const float* q  = (const float*)d_in[0];
    const float* Wq = (const float*)d_in[1];
    const float* bq = (const float*)d_in[2];
    const float* Wk = (const float*)d_in[3];
    const float* bk = (const float*)d_in[4];
    const float* Wv = (const float*)d_in[5];
    const float* bv = (const float*)d_in[6];
    const float* Wo = (const float*)d_in[7];
    const float* bo = (const float*)d_in[8];
    float* out = (float*)d_out;

    float *gq, *gk, *gv, *go;
    cudaGetSymbolAddress((void**)&gq, g_Q);
    cudaGetSymbolAddress((void**)&gk, g_K);
    cudaGetSymbolAddress((void**)&gv, g_V);
    cudaGetSymbolAddress((void**)&go, g_O);

    QKVArgs args;
    args.W[0] = Wq; args.W[1] = Wk; args.W[2] = Wv;
    args.bias[0] = bq; args.bias[1] = bk; args.bias[2] = bv;
    args.C[0] = gq; args.C[1] = gk; args.C[2] = gv;

    const dim3 gqkv(DMODEL/128, MTOT/128, 3);  // (8, 32, 3)
    qkv_kernel<<<gqkv, 256>>>(q, args);

    cudaFuncSetAttribute(flash_kernel,
                         cudaFuncAttributeMaxDynamicSharedMemorySize,
                         FLASH_SMEM_BYTES);
    flash_kernel<<<dim3(SEQ/128, BATCH*NHEAD), 256, FLASH_SMEM_BYTES>>>(gq, gk, gv, go);

    oproj_kernel<<<dim3(DMODEL/128, MTOT/128), 256>>>(go, Wo, bo, out);
}

// round 16
// speedup vs baseline: 1.0347x; 1.0347x over previous
#include <cuda_runtime.h>

// Problem constants
#define BATCH  2
#define SEQ    2048
#define DMODEL 1024
#define NHEAD  16
#define HSIZE  64
#define MTOT   (BATCH*SEQ)   // 4096

// Scratch (device globals: allocation-free per harness rules)
__device__ float g_Q[BATCH*NHEAD*SEQ*HSIZE];  // [B,H,S,HS]
__device__ float g_K[BATCH*NHEAD*SEQ*HSIZE];
__device__ float g_V[BATCH*NHEAD*SEQ*HSIZE];
__device__ float g_O[(size_t)MTOT*DMODEL];    // [B*S, D]

struct QKVArgs {
    const float* W[3];
    const float* bias[3];
    float*       C[3];
};

// ---------------------------------------------------------------------------
// TF32 / math helpers
// ---------------------------------------------------------------------------
__device__ __forceinline__ float tf32r(float x) {  // round to tf32, keep float bits
    unsigned u;
    asm("cvt.rna.tf32.f32 %0, %1;" : "=r"(u) : "f"(x));
    return __uint_as_float(u);
}

__device__ __forceinline__ float fexp2(float x) {  // raw MUFU ex2
    float y;
    asm("ex2.approx.ftz.f32 %0, %1;" : "=f"(y) : "f"(x));
    return y;
}

__device__ __forceinline__ void mma_tf32_16x8x8(
    float c[4], const unsigned a[4], const unsigned b[2])
{
    asm volatile(
        "mma.sync.aligned.m16n8k8.row.col.f32.tf32.tf32.f32 "
        "{%0,%1,%2,%3}, {%4,%5,%6,%7}, {%8,%9}, {%0,%1,%2,%3};\n"
        : "+f"(c[0]), "+f"(c[1]), "+f"(c[2]), "+f"(c[3])
        : "r"(a[0]), "r"(a[1]), "r"(a[2]), "r"(a[3]),
          "r"(b[0]), "r"(b[1]));
}

// Smem generic->shared 32-bit address
__device__ __forceinline__ unsigned s2u(const void* p) {
    unsigned a;
    asm("{ .reg .u64 t; cvta.to.shared.u64 t, %1; cvt.u32.u64 %0, t; }"
        : "=r"(a) : "l"(p));
    return a;
}

// ldmatrix x4 (b16, non-trans): for 32-bit data this loads the full tf32
// m16n8k8 A-fragment in one instruction when addresses are arranged as
// lanes 0-7 -> (rows 0-7, col 0), 8-15 -> (rows 8-15, col 0),
// 16-23 -> (rows 0-7, col 4), 24-31 -> (rows 8-15, col 4).
__device__ __forceinline__ void ldsm_x4(unsigned r[4], unsigned saddr) {
    asm volatile(
        "ldmatrix.sync.aligned.m8n8.x4.shared.b16 {%0,%1,%2,%3}, [%4];"
        : "=r"(r[0]), "=r"(r[1]), "=r"(r[2]), "=r"(r[3]) : "r"(saddr));
}

#define FAU(x) __float_as_uint(x)

// ---------------------------------------------------------------------------
// TF32 GEMM body: C[4096,1024] = A[4096,1024] @ W[1024,1024] + bias
// BM=BN=128, BK=8, 256 thr = 8 warps (4 x 2); warp tile 32x64 = 2x8 mmas.
// Double-buffered smem (tf32-preconverted), register prefetch, 1 barrier/step.
// A-fragments via ldmatrix.x4 (stride 12 -> phase banks 48l mod 128, all
// distinct: conflict-free). B stride 136 (bank 8t+g): conflict-free scalar.
// PERM=true scatters output into [B,H,S,HS] layout for attention.
// ---------------------------------------------------------------------------
#define ASTRIDE 12
#define BSTRIDE 136

template<bool PERM>
__device__ __forceinline__ void tf32_gemm_body(
    const float* __restrict__ A, const float* __restrict__ Bm,
    const float* __restrict__ bias, float* __restrict__ C)
{
    __shared__ float As[2][128*ASTRIDE];   // [m][k] padded, tf32 values
    __shared__ float Bs[2][8*BSTRIDE];     // [k][n] padded, tf32 values

    const int bm   = blockIdx.y * 128;
    const int bn   = blockIdx.x * 128;
    const int tid  = threadIdx.x;
    const int lane = tid & 31;
    const int warp = tid >> 5;
    const int wm   = warp & 3;    // 0..3 -> M offset wm*32
    const int wn   = warp >> 2;   // 0..1 -> N offset wn*64

    const int g = lane >> 2;      // 0..7
    const int t = lane & 3;       // 0..3

    const int arow = tid >> 1;           // 0..127
    const int acol = (tid & 1) << 2;     // 0 or 4
    const int brow = tid >> 5;           // 0..7
    const int bcol = (tid & 31) << 2;    // 0..124

    const float* Ap = A  + (size_t)(bm + arow) * DMODEL + acol;
    const float* Bp = Bm + (size_t)brow * DMODEL + bn + bcol;

    // ldmatrix base address for this lane (tile layout per helper comment)
    const int lrow = lane & 15;               // row within m16
    const int lcol = (lane & 16) ? 4 : 0;     // k-column half
    const unsigned aBase = s2u(&As[0][0]) +
        (unsigned)(((wm*32 + lrow)*ASTRIDE + lcol) * 4);
    const unsigned aBufStep = 128*ASTRIDE*4;  // As[0] -> As[1]
    const unsigned aMtStep  = 16*ASTRIDE*4;   // mt 0 -> 1

    float acc[2][8][4];
    #pragma unroll
    for (int mt = 0; mt < 2; ++mt)
        #pragma unroll
        for (int nt = 0; nt < 8; ++nt)
            #pragma unroll
            for (int r = 0; r < 4; ++r) acc[mt][nt][r] = 0.f;

    // Prologue: fill buffer 0 (converted)
    {
        float4 av = *(const float4*)(Ap);
        float4 bv = *(const float4*)(Bp);
        float4 ac = make_float4(tf32r(av.x), tf32r(av.y), tf32r(av.z), tf32r(av.w));
        float4 bc = make_float4(tf32r(bv.x), tf32r(bv.y), tf32r(bv.z), tf32r(bv.w));
        *(float4*)&As[0][arow*ASTRIDE + acol] = ac;
        *(float4*)&Bs[0][brow*BSTRIDE + bcol] = bc;
    }
    __syncthreads();

    int buf = 0;
    for (int k0 = 8; ; k0 += 8) {
        const bool more = (k0 < DMODEL);
        float4 av2, bv2;
        if (more) {
            av2 = *(const float4*)(Ap + k0);
            bv2 = *(const float4*)(Bp + (size_t)k0 * DMODEL);
        }

        unsigned aF[2][4];
        const unsigned aAddr = aBase + (unsigned)buf * aBufStep;
        ldsm_x4(aF[0], aAddr);
        ldsm_x4(aF[1], aAddr + aMtStep);
        #pragma unroll
        for (int nt = 0; nt < 8; ++nt) {
            const int c0 = wn*64 + nt*8 + g;
            unsigned bF[2];
            bF[0] = FAU(Bs[buf][(t    )*BSTRIDE + c0]);
            bF[1] = FAU(Bs[buf][(t + 4)*BSTRIDE + c0]);
            mma_tf32_16x8x8(acc[0][nt], aF[0], bF);
            mma_tf32_16x8x8(acc[1][nt], aF[1], bF);
        }

        if (!more) break;

        const int nb = buf ^ 1;
        float4 ac = make_float4(tf32r(av2.x), tf32r(av2.y), tf32r(av2.z), tf32r(av2.w));
        float4 bc = make_float4(tf32r(bv2.x), tf32r(bv2.y), tf32r(bv2.z), tf32r(bv2.w));
        *(float4*)&As[nb][arow*ASTRIDE + acol] = ac;
        *(float4*)&Bs[nb][brow*BSTRIDE + bcol] = bc;
        __syncthreads();
        buf = nb;
    }

    // Epilogue: c0,c1 at (row, 2t), (row, 2t+1); c2,c3 at row+8
    #pragma unroll
    for (int mt = 0; mt < 2; ++mt) {
        #pragma unroll
        for (int nt = 0; nt < 8; ++nt) {
            const int c = bn + wn*64 + nt*8 + 2*t;
            const float bx = bias[c], by = bias[c+1];
            #pragma unroll
            for (int half = 0; half < 2; ++half) {
                const int r = bm + wm*32 + mt*16 + g + half*8;
                float2 v;
                v.x = acc[mt][nt][half*2+0] + bx;
                v.y = acc[mt][nt][half*2+1] + by;
                if (PERM) {
                    const int b  = r >> 11;       // r / SEQ
                    const int s  = r & (SEQ-1);
                    const int h  = c >> 6;        // c / HSIZE
                    const int hs = c & 63;
                    *(float2*)&C[(((size_t)(b*NHEAD + h))*SEQ + s)*HSIZE + hs] = v;
                } else {
                    *(float2*)&C[(size_t)r*DMODEL + c] = v;
                }
            }
        }
    }
}

__global__ __launch_bounds__(256, 2) void qkv_kernel(
    const float* __restrict__ A, QKVArgs args)
{
    const int z = blockIdx.z;
    tf32_gemm_body<true>(A, args.W[z], args.bias[z], args.C[z]);
}

__global__ __launch_bounds__(256, 2) void oproj_kernel(
    const float* __restrict__ A, const float* __restrict__ W,
    const float* __restrict__ bias, float* __restrict__ C)
{
    tf32_gemm_body<false>(A, W, bias, C);
}

// ---------------------------------------------------------------------------
// TF32-mma causal flash attention.
// CTA = 128 q-rows x one (b,h). 256 threads = 8 warps; warp w owns q-rows
// [w*16, w*16+16) and the full 64-key / 64-hs extent.
// Qs/Ps use stride 76 (ldmatrix phase banks 48l mod 128: conflict-free);
// Ks/Vs keep stride 72 (B-frag banks 8g+t / 8t+g: conflict-free).
// Q and P A-fragments via ldmatrix.x4.
// Softmax in exp2 domain (log2(e)/8 folded into Q scale).
// P staged through warp-private smem rows (-> __syncwarp only).
// Fully-masked warps on trailing tiles skip compute.
// smem: 2*(128*76) + 2*(64*72) floats = 114688 B -> 2 CTAs/SM.
// ---------------------------------------------------------------------------
#define FSTRQ 76
#define FSTRKV 72
#define FLASH_SMEM_BYTES ((2*128*FSTRQ + 2*64*FSTRKV)*4)   // 114688
#define QSCALE (0.125f * 1.4426950408889634f)              // 1/sqrt(64)*log2(e)

__global__ __launch_bounds__(256, 2) void flash_kernel(
    const float* __restrict__ Q, const float* __restrict__ K,
    const float* __restrict__ V, float* __restrict__ O)
{
    extern __shared__ float sm[];
    float* Qs = sm;                          // [q][d]    stride 76
    float* Ks = sm + 128*FSTRQ;              // [key][d]  stride 72
    float* Vs = Ks + 64*FSTRKV;              // [key][hs] stride 72
    float* Ps = Vs + 64*FSTRKV;              // [q][key]  stride 76

    const int qtile = (gridDim.x - 1) - blockIdx.x;  // heavy tiles first
    const int bh    = blockIdx.y;
    const int tid   = threadIdx.x;
    const int lane  = tid & 31;
    const int warp  = tid >> 5;      // 0..7
    const int g     = lane >> 2;     // 0..7
    const int t     = lane & 3;      // 0..3
    const int qr    = warp * 16;     // warp's local q-row base

    const size_t base = (size_t)bh * SEQ * HSIZE;
    const float* Qb = Q + base;
    const float* Kb = K + base;
    const float* Vb = V + base;
    const int q0 = qtile * 128;

    // ldmatrix lane address components (rows qr..qr+15, col halves 0/4)
    const int lrow = lane & 15;
    const int lcol = (lane & 16) ? 4 : 0;
    const unsigned qAddr0 = s2u(Qs) + (unsigned)(((qr + lrow)*FSTRQ + lcol)*4);
    const unsigned pAddr0 = s2u(Ps) + (unsigned)(((qr + lrow)*FSTRQ + lcol)*4);

    // Load Q tile [128][64], fold QSCALE, convert to tf32
    for (int idx = tid; idx < 2048; idx += 256) {
        const int r = idx >> 4;
        const int c = (idx & 15) << 2;
        float4 v = *(const float4*)(Qb + (size_t)(q0 + r)*HSIZE + c);
        float* dst = &Qs[r*FSTRQ + c];
        dst[0] = tf32r(v.x * QSCALE);
        dst[1] = tf32r(v.y * QSCALE);
        dst[2] = tf32r(v.z * QSCALE);
        dst[3] = tf32r(v.w * QSCALE);
    }

    float oF[8][4];
    #pragma unroll
    for (int nt = 0; nt < 8; ++nt)
        #pragma unroll
        for (int r = 0; r < 4; ++r) oF[nt][r] = 0.f;
    float m0 = -1e30f, m1 = -1e30f, l0 = 0.f, l1 = 0.f;

    const int nkt = 2*qtile + 2;     // key tiles covering [0, q0+128)
    for (int kt = 0; kt < nkt; ++kt) {
        __syncthreads();             // prior tile reads done (Qs ready 1st iter)
        const int k0 = kt * 64;

        // Load K and V tiles row-major, tf32-converted (coalesced float4)
        for (int idx = tid; idx < 1024; idx += 256) {
            const int r = idx >> 4;
            const int c = (idx & 15) << 2;
            float4 kv = *(const float4*)(Kb + (size_t)(k0 + r)*HSIZE + c);
            float* kd = &Ks[r*FSTRKV + c];
            kd[0] = tf32r(kv.x);
            kd[1] = tf32r(kv.y);
            kd[2] = tf32r(kv.z);
            kd[3] = tf32r(kv.w);
            float4 vv = *(const float4*)(Vb + (size_t)(k0 + r)*HSIZE + c);
            float* vd = &Vs[r*FSTRKV + c];
            vd[0] = tf32r(vv.x);
            vd[1] = tf32r(vv.y);
            vd[2] = tf32r(vv.z);
            vd[3] = tf32r(vv.w);
        }
        __syncthreads();

        // Warp fully below the diagonal band? Skip all compute.
        if (q0 + qr + 15 < k0) continue;

        // ---- S' = (Q*QSCALE) K^T  (log2-domain scores) ----
        float sF[8][4];
        #pragma unroll
        for (int nt = 0; nt < 8; ++nt)
            #pragma unroll
            for (int r = 0; r < 4; ++r) sF[nt][r] = 0.f;

        #pragma unroll
        for (int ks = 0; ks < 8; ++ks) {
            unsigned aF[4];
            ldsm_x4(aF, qAddr0 + (unsigned)(ks*32));
            #pragma unroll
            for (int nt = 0; nt < 8; ++nt) {
                unsigned bF[2];
                bF[0] = FAU(Ks[(nt*8 + g)*FSTRKV + ks*8 + t    ]);
                bF[1] = FAU(Ks[(nt*8 + g)*FSTRKV + ks*8 + t + 4]);
                mma_tf32_16x8x8(sF[nt], aF, bF);
            }
        }

        // ---- causal mask (only tiles straddling the diagonal) ----
        const int qg0 = q0 + qr + g;
        const int qg1 = qg0 + 8;
        if (k0 + 63 > q0 + qr) {
            #pragma unroll
            for (int nt = 0; nt < 8; ++nt) {
                const int j0 = k0 + nt*8 + 2*t;
                if (j0     > qg0) sF[nt][0] = -1e30f;
                if (j0 + 1 > qg0) sF[nt][1] = -1e30f;
                if (j0     > qg1) sF[nt][2] = -1e30f;
                if (j0 + 1 > qg1) sF[nt][3] = -1e30f;
            }
        }

        // ---- online softmax in exp2 domain (rows g and g+8) ----
        float mt0 = -1e30f, mt1 = -1e30f;
        #pragma unroll
        for (int nt = 0; nt < 8; ++nt) {
            mt0 = fmaxf(mt0, fmaxf(sF[nt][0], sF[nt][1]));
            mt1 = fmaxf(mt1, fmaxf(sF[nt][2], sF[nt][3]));
        }
        mt0 = fmaxf(mt0, __shfl_xor_sync(0xffffffffu, mt0, 1));
        mt0 = fmaxf(mt0, __shfl_xor_sync(0xffffffffu, mt0, 2));
        mt1 = fmaxf(mt1, __shfl_xor_sync(0xffffffffu, mt1, 1));
        mt1 = fmaxf(mt1, __shfl_xor_sync(0xffffffffu, mt1, 2));

        const float m0n = fmaxf(m0, mt0);
        const float m1n = fmaxf(m1, mt1);
        const float sc0 = fexp2(m0 - m0n);
        const float sc1 = fexp2(m1 - m1n);

        float rs0 = 0.f, rs1 = 0.f;
        #pragma unroll
        for (int nt = 0; nt < 8; ++nt) {
            sF[nt][0] = fexp2(sF[nt][0] - m0n); rs0 += sF[nt][0];
            sF[nt][1] = fexp2(sF[nt][1] - m0n); rs0 += sF[nt][1];
            sF[nt][2] = fexp2(sF[nt][2] - m1n); rs1 += sF[nt][2];
            sF[nt][3] = fexp2(sF[nt][3] - m1n); rs1 += sF[nt][3];
        }
        rs0 += __shfl_xor_sync(0xffffffffu, rs0, 1);
        rs0 += __shfl_xor_sync(0xffffffffu, rs0, 2);
        rs1 += __shfl_xor_sync(0xffffffffu, rs1, 1);
        rs1 += __shfl_xor_sync(0xffffffffu, rs1, 2);

        l0 = l0*sc0 + rs0;  m0 = m0n;
        l1 = l1*sc1 + rs1;  m1 = m1n;

        #pragma unroll
        for (int nt = 0; nt < 8; ++nt) {
            oF[nt][0] *= sc0; oF[nt][1] *= sc0;
            oF[nt][2] *= sc1; oF[nt][3] *= sc1;
        }

        // ---- stage P (tf32) into warp-private smem rows ----
        #pragma unroll
        for (int nt = 0; nt < 8; ++nt) {
            float2 p0; p0.x = tf32r(sF[nt][0]); p0.y = tf32r(sF[nt][1]);
            float2 p1; p1.x = tf32r(sF[nt][2]); p1.y = tf32r(sF[nt][3]);
            *(float2*)&Ps[(qr+g  )*FSTRQ + nt*8 + 2*t] = p0;
            *(float2*)&Ps[(qr+g+8)*FSTRQ + nt*8 + 2*t] = p1;
        }
        __syncwarp();

        // ---- O += P @ V ----
        #pragma unroll
        for (int ks = 0; ks < 8; ++ks) {
            unsigned aP[4];
            ldsm_x4(aP, pAddr0 + (unsigned)(ks*32));
            #pragma unroll
            for (int nt = 0; nt < 8; ++nt) {
                unsigned bV[2];
                bV[0] = FAU(Vs[(ks*8 + t    )*FSTRKV + nt*8 + g]);
                bV[1] = FAU(Vs[(ks*8 + t + 4)*FSTRKV + nt*8 + g]);
                mma_tf32_16x8x8(oF[nt], aP, bV);
            }
        }
    }

    // ---- epilogue: normalize, write [B*S, D] scratch ----
    const int bidx = bh >> 4;
    const int h    = bh & 15;
    const int qg0  = q0 + qr + g;
    const int qg1  = qg0 + 8;
    const float inv0 = 1.f / l0;
    const float inv1 = 1.f / l1;
    #pragma unroll
    for (int nt = 0; nt < 8; ++nt) {
        const int c = h*HSIZE + nt*8 + 2*t;
        float2 v0; v0.x = oF[nt][0]*inv0; v0.y = oF[nt][1]*inv0;
        float2 v1; v1.x = oF[nt][2]*inv1; v1.y = oF[nt][3]*inv1;
        *(float2*)&O[((size_t)(bidx*SEQ + qg0))*DMODEL + c] = v0;
        *(float2*)&O[((size_t)(bidx*SEQ + qg1))*DMODEL + c] = v1;
    }
}

// ---------------------------------------------------------------------------
extern "C" void kernel_launch(void* const* d_in, const int* in_sizes, int n_in,
                              void* d_out, int out_size)
{
    const float* q  = (const float*)d_in[0];
    const float* Wq = (const float*)d_in[1];
    const float* bq = (const float*)d_in[2];
    const float* Wk = (const float*)d_in[3];
    const float* bk = (const float*)d_in[4];
    const float* Wv = (const float*)d_in[5];
    const float* bv = (const float*)d_in[6];
    const float* Wo = (const float*)d_in[7];
    const float* bo = (const float*)d_in[8];
    float* out = (float*)d_out;

    float *gq, *gk, *gv, *go;
    cudaGetSymbolAddress((void**)&gq, g_Q);
    cudaGetSymbolAddress((void**)&gk, g_K);
    cudaGetSymbolAddress((void**)&gv, g_V);
    cudaGetSymbolAddress((void**)&go, g_O);

    QKVArgs args;
    args.W[0] = Wq; args.W[1] = Wk; args.W[2] = Wv;
    args.bias[0] = bq; args.bias[1] = bk; args.bias[2] = bv;
    args.C[0] = gq; args.C[1] = gk; args.C[2] = gv;

    const dim3 gqkv(DMODEL/128, MTOT/128, 3);  // (8, 32, 3)
    qkv_kernel<<<gqkv, 256>>>(q, args);

    cudaFuncSetAttribute(flash_kernel,
                         cudaFuncAttributeMaxDynamicSharedMemorySize,
                         FLASH_SMEM_BYTES);
    flash_kernel<<<dim3(SEQ/128, BATCH*NHEAD), 256, FLASH_SMEM_BYTES>>>(gq, gk, gv, go);

    oproj_kernel<<<dim3(DMODEL/128, MTOT/128), 256>>>(go, Wo, bo, out);
}